// round 1
// baseline (speedup 1.0000x reference)
#include <cuda_runtime.h>
#include <cuda_bf16.h>

// ---------------------------------------------------------------------------
// FixedHiddenMLP: out = scale_to_le1( sum( relu( (X@W^T + b) @ R + 1 ) ) )
// Folded:  M[k][m] = sum_j W[j,k]*R[j,m],  c[m] = sum_j b[j]*R[j,m] + 1
//          h[i,m]  = relu( sum_k X[i,k]*M[k,m] + c[m] )
// Output is a single f32 scalar: S * 2^-n with n = #halvings until <= 1.
// ---------------------------------------------------------------------------

#define D 20  // feature dim

__device__ double g_sum;  // scratch accumulator (zeroed by a tiny kernel)

// --- packed f32x2 helpers (FFMA2 only reachable via PTX) -------------------
__device__ __forceinline__ unsigned long long pack2(float lo, float hi) {
    unsigned long long r;
    asm("mov.b64 %0, {%1, %2};" : "=l"(r) : "f"(lo), "f"(hi));
    return r;
}
__device__ __forceinline__ void unpack2(unsigned long long v, float& lo, float& hi) {
    asm("mov.b64 {%0, %1}, %2;" : "=f"(lo), "=f"(hi) : "l"(v));
}
__device__ __forceinline__ unsigned long long fma2(unsigned long long a,
                                                   unsigned long long b,
                                                   unsigned long long c) {
    unsigned long long d;
    asm("fma.rn.f32x2 %0, %1, %2, %3;" : "=l"(d) : "l"(a), "l"(b), "l"(c));
    return d;
}

__global__ void zero_kernel() { g_sum = 0.0; }

__global__ void __launch_bounds__(256, 2)
mlp_sum_kernel(const float* __restrict__ X,
               const float* __restrict__ W,
               const float* __restrict__ b,
               const float* __restrict__ R,
               long long nrows)
{
    // Duplicated (m,m) pairs so FFMA2's B operand needs no lane swizzle.
    __shared__ unsigned long long sM[D][D];   // sM[k][m] = (M[k][m], M[k][m])
    __shared__ unsigned long long sC[D];      // sC[m]    = (c[m], c[m])
    __shared__ double sred[256];

    const int tid = threadIdx.x;

    // --- fold the two tiny matmuls (trivial: 400 entries x 20 FMA) --------
    for (int idx = tid; idx < D * D; idx += blockDim.x) {
        const int k = idx / D, m = idx % D;
        float acc = 0.f;
        #pragma unroll
        for (int j = 0; j < D; ++j)
            acc += W[j * D + k] * R[j * D + m];
        sM[k][m] = pack2(acc, acc);
    }
    if (tid < D) {
        float acc = 1.f;
        #pragma unroll
        for (int j = 0; j < D; ++j)
            acc += b[j] * R[j * D + tid];
        sC[tid] = pack2(acc, acc);
    }
    __syncthreads();

    // --- main streaming pass: 2 rows per thread iteration ------------------
    const long long npairs = nrows >> 1;
    const long long stride = (long long)gridDim.x * blockDim.x;
    double dacc = 0.0;

    for (long long p = (long long)blockIdx.x * blockDim.x + tid; p < npairs; p += stride) {
        // two adjacent rows: 80 B each, 16B-aligned -> 10x float4
        const float4* __restrict__ pr = (const float4*)(X + p * (2 * D));
        float a[2 * D];
        #pragma unroll
        for (int q = 0; q < 10; ++q) {
            float4 t = pr[q];
            a[4 * q + 0] = t.x; a[4 * q + 1] = t.y;
            a[4 * q + 2] = t.z; a[4 * q + 3] = t.w;
        }
        // pack (row0[k], row1[k]) once per k; reused across all 20 outputs
        unsigned long long xp[D];
        #pragma unroll
        for (int k = 0; k < D; ++k)
            xp[k] = pack2(a[k], a[D + k]);

        float rs = 0.f;
        #pragma unroll
        for (int m = 0; m < D; ++m) {
            unsigned long long acc = sC[m];
            #pragma unroll
            for (int k = 0; k < D; ++k)
                acc = fma2(xp[k], sM[k][m], acc);   // 2 rows per FFMA2
            float lo, hi;
            unpack2(acc, lo, hi);
            rs += fmaxf(lo, 0.f) + fmaxf(hi, 0.f);  // relu + row sums
        }
        dacc += (double)rs;   // fp64 accumulation: 4e7 terms need it
    }

    // odd-row tail (nrows is even here, but stay generic)
    if ((nrows & 1) && blockIdx.x == 0 && tid == 0) {
        const float* xr = X + (nrows - 1) * D;
        float rs = 0.f;
        for (int m = 0; m < D; ++m) {
            float lo, hi; unpack2(sC[m], lo, hi);
            float acc = lo;
            for (int k = 0; k < D; ++k) {
                float mlo, mhi; unpack2(sM[k][m], mlo, mhi);
                acc += xr[k] * mlo;
            }
            rs += fmaxf(acc, 0.f);
        }
        dacc += (double)rs;
    }

    // --- block reduce (double) + one global atomic per block ---------------
    sred[tid] = dacc;
    __syncthreads();
    for (int s = 128; s > 0; s >>= 1) {
        if (tid < s) sred[tid] += sred[tid + s];
        __syncthreads();
    }
    if (tid == 0) atomicAdd(&g_sum, sred[0]);
}

__global__ void finalize_kernel(float* __restrict__ out) {
    float v = (float)g_sum;
    int n = 0;
    // exact power-of-two halving, same as reference's while-loop semantics
    while (v > 1.0f && n < 4096) { v *= 0.5f; ++n; }
    out[0] = v;
}

extern "C" void kernel_launch(void* const* d_in, const int* in_sizes, int n_in,
                              void* d_out, int out_size)
{
    const float* X = (const float*)d_in[0];
    const float* W = (const float*)d_in[1];
    const float* b = (const float*)d_in[2];
    const float* R = (const float*)d_in[3];
    float* out = (float*)d_out;

    const long long nrows = (long long)in_sizes[0] / D;

    zero_kernel<<<1, 1>>>();
    const int blocks = 148 * 8;  // grid-stride; ~8 CTAs/SM worth of work slices
    mlp_sum_kernel<<<blocks, 256>>>(X, W, b, R, nrows);
    finalize_kernel<<<1, 1>>>(out);
}

// round 2
// speedup vs baseline: 3.7968x; 3.7968x over previous
#include <cuda_runtime.h>
#include <cuda_bf16.h>

// ---------------------------------------------------------------------------
// FixedHiddenMLP: out = scale_to_le1( sum( relu( (X@W^T + b) @ R + 1 ) ) )
// Folded:  M[k][m] = sum_j W[j,k]*R[j,m],  c[m] = sum_j b[j]*R[j,m] + 1
//          h[i,m]  = relu( sum_k X[i,k]*M[k,m] + c[m] )
// Output is a single f32 scalar: S * 2^-n with n = #halvings until <= 1.
//
// Round 2: scalar-FFMA version, deliberately boring codegen.
//   - 1 row/thread, k-outer m-inner, 20 independent fp32 accumulators (ILP).
//   - sM staged in smem as float4 rows -> broadcast LDS.128.
//   - ~64 regs/thread, no launch_bounds min-blocks clamp, no inline asm.
//   - per-block partial sums (overwritten, no zeroing kernel needed).
// ---------------------------------------------------------------------------

#define D 20
#define NBLOCKS 1184            // 148 SMs * 8
#define NTHREADS 256

__device__ double g_part[NBLOCKS];

__global__ void __launch_bounds__(NTHREADS)
mlp_sum_kernel(const float* __restrict__ X,
               const float* __restrict__ W,
               const float* __restrict__ b,
               const float* __restrict__ R,
               long long nrows)
{
    __shared__ float4 sM4[D][5];    // sM4[k][q] = M[k][4q..4q+3]
    __shared__ float  sC[D];
    __shared__ double sred[NTHREADS];

    const int tid = threadIdx.x;

    // --- fold the two tiny matmuls: M = W^T(?) folded with R ---------------
    // M[k][m] = sum_j W[j*D+k] * R[j*D+m]
    for (int idx = tid; idx < D * D; idx += NTHREADS) {
        const int k = idx / D, m = idx % D;
        float acc = 0.f;
        #pragma unroll
        for (int j = 0; j < D; ++j)
            acc += W[j * D + k] * R[j * D + m];
        ((float*)&sM4[k][0])[m] = acc;
    }
    if (tid < D) {
        float acc = 1.f;
        #pragma unroll
        for (int j = 0; j < D; ++j)
            acc += b[j] * R[j * D + tid];
        sC[tid] = acc;
    }
    __syncthreads();

    // --- streaming pass: one row per thread per iteration ------------------
    const long long stride = (long long)gridDim.x * NTHREADS;
    double dacc = 0.0;

    for (long long r = (long long)blockIdx.x * NTHREADS + tid; r < nrows; r += stride) {
        const float4* __restrict__ pr = (const float4*)(X + r * D);
        float x[D];
        #pragma unroll
        for (int q = 0; q < 5; ++q) {
            const float4 t = pr[q];
            x[4 * q + 0] = t.x; x[4 * q + 1] = t.y;
            x[4 * q + 2] = t.z; x[4 * q + 3] = t.w;
        }

        float acc[D];
        #pragma unroll
        for (int m = 0; m < D; ++m) acc[m] = sC[m];

        #pragma unroll
        for (int k = 0; k < D; ++k) {
            const float xk = x[k];
            #pragma unroll
            for (int q = 0; q < 5; ++q) {
                const float4 mv = sM4[k][q];            // broadcast LDS.128
                acc[4 * q + 0] = fmaf(xk, mv.x, acc[4 * q + 0]);
                acc[4 * q + 1] = fmaf(xk, mv.y, acc[4 * q + 1]);
                acc[4 * q + 2] = fmaf(xk, mv.z, acc[4 * q + 2]);
                acc[4 * q + 3] = fmaf(xk, mv.w, acc[4 * q + 3]);
            }
        }

        float rs = 0.f;
        #pragma unroll
        for (int m = 0; m < D; ++m) rs += fmaxf(acc[m], 0.f);
        dacc += (double)rs;
    }

    // --- block reduce (double) ---------------------------------------------
    sred[tid] = dacc;
    __syncthreads();
    #pragma unroll
    for (int s = NTHREADS / 2; s > 0; s >>= 1) {
        if (tid < s) sred[tid] += sred[tid + s];
        __syncthreads();
    }
    if (tid == 0) g_part[blockIdx.x] = sred[0];   // overwrite: no zeroing pass
}

__global__ void __launch_bounds__(NTHREADS)
finalize_kernel(float* __restrict__ out, int nblocks)
{
    __shared__ double sred[NTHREADS];
    const int tid = threadIdx.x;

    double acc = 0.0;
    for (int i = tid; i < nblocks; i += NTHREADS) acc += g_part[i];
    sred[tid] = acc;
    __syncthreads();
    #pragma unroll
    for (int s = NTHREADS / 2; s > 0; s >>= 1) {
        if (tid < s) sred[tid] += sred[tid + s];
        __syncthreads();
    }

    if (tid == 0) {
        float v = (float)sred[0];
        int n = 0;
        while (v > 1.0f && n < 4096) { v *= 0.5f; ++n; }  // exact /2 halvings
        out[0] = v;
    }
}

extern "C" void kernel_launch(void* const* d_in, const int* in_sizes, int n_in,
                              void* d_out, int out_size)
{
    const float* X = (const float*)d_in[0];
    const float* W = (const float*)d_in[1];
    const float* b = (const float*)d_in[2];
    const float* R = (const float*)d_in[3];
    float* out = (float*)d_out;

    const long long nrows = (long long)in_sizes[0] / D;

    mlp_sum_kernel<<<NBLOCKS, NTHREADS>>>(X, W, b, R, nrows);
    finalize_kernel<<<1, NTHREADS>>>(out, NBLOCKS);
}

// round 4
// speedup vs baseline: 4.2148x; 1.1101x over previous
#include <cuda_runtime.h>
#include <cuda_bf16.h>

// ---------------------------------------------------------------------------
// FixedHiddenMLP -> single scalar: scale_to_le1( sum relu( X@M + c ) )
//   M[k][m] = sum_j W[j,k]*R[j,m],  c[m] = sum_j b[j]*R[j,m] + 1
//
// Round 4: identical to round 3 EXCEPT fold_kernel now covers all 400
// entries (round 3 wrote only 256 of 400 -> 4.5e-2 rel_err).
//  - f32x2 (FFMA2) packing over m-pairs: a=(xk,xk), b=(M[k][2q],M[k][2q+1]).
//  - 2 rows/thread: each LDS.128 of packed M feeds both rows.
//  - 4-kernel graph so ncu's 6th-launch capture lands on the MAIN kernel.
// ---------------------------------------------------------------------------

#define D 20
#define NB 1184                 // 148 * 8 blocks
#define NT 128                  // threads per block

__device__ float  gM[D * D];    // folded matrix
__device__ float  gC[D];        // folded bias (+1)
__device__ double g_part[NB];
__device__ float  g_dummy;

// --- f32x2 helpers ---------------------------------------------------------
__device__ __forceinline__ unsigned long long pack2(float lo, float hi) {
    unsigned long long r;
    asm("mov.b64 %0, {%1, %2};" : "=l"(r) : "f"(lo), "f"(hi));
    return r;
}
__device__ __forceinline__ void unpack2(unsigned long long v, float& lo, float& hi) {
    asm("mov.b64 {%0, %1}, %2;" : "=f"(lo), "=f"(hi) : "l"(v));
}
__device__ __forceinline__ unsigned long long fma2(unsigned long long a,
                                                   unsigned long long b,
                                                   unsigned long long c) {
    unsigned long long d;
    asm("fma.rn.f32x2 %0, %1, %2, %3;" : "=l"(d) : "l"(a), "l"(b), "l"(c));
    return d;
}

// --- kernel 1: fold the two tiny matmuls ----------------------------------
__global__ void fold_kernel(const float* __restrict__ W,
                            const float* __restrict__ b,
                            const float* __restrict__ R)
{
    // grid-stride: 400 entries > 256 threads (round-3 bug was a bare `if`)
    for (int idx = threadIdx.x; idx < D * D; idx += blockDim.x) {
        const int k = idx / D, m = idx % D;
        float acc = 0.f;
        #pragma unroll
        for (int j = 0; j < D; ++j)
            acc += W[j * D + k] * R[j * D + m];
        gM[idx] = acc;
    }
    if (threadIdx.x < D) {
        float acc = 1.f;
        #pragma unroll
        for (int j = 0; j < D; ++j)
            acc += b[j] * R[j * D + threadIdx.x];
        gC[threadIdx.x] = acc;
    }
}

// --- kernel 2: main streaming pass ----------------------------------------
__global__ void __launch_bounds__(NT)
mlp_sum_kernel(const float* __restrict__ X, long long nrows)
{
    // packed M: sM2[k][q] = (M[k][2q], M[k][2q+1]); read as ulonglong2 pairs
    __shared__ unsigned long long sM2[D][10];
    __shared__ unsigned long long sC2[10];
    __shared__ double sred[NT];

    const int tid = threadIdx.x;

    for (int i = tid; i < D * 10; i += NT) {
        const int k = i / 10, q = i % 10;
        sM2[k][q] = pack2(gM[k * D + 2 * q], gM[k * D + 2 * q + 1]);
    }
    if (tid < 10) sC2[tid] = pack2(gC[2 * tid], gC[2 * tid + 1]);
    __syncthreads();

    const long long npairs = nrows >> 1;
    const long long stride = (long long)gridDim.x * NT;
    double dacc = 0.0;

    for (long long p = (long long)blockIdx.x * NT + tid; p < npairs; p += stride) {
        // two adjacent rows (160B, 16B aligned) -> 10x LDG.128
        const float4* __restrict__ pr = (const float4*)(X + p * (2 * D));
        float x0[D], x1[D];
        #pragma unroll
        for (int q = 0; q < 5; ++q) {
            const float4 t = pr[q];
            x0[4 * q + 0] = t.x; x0[4 * q + 1] = t.y;
            x0[4 * q + 2] = t.z; x0[4 * q + 3] = t.w;
        }
        #pragma unroll
        for (int q = 0; q < 5; ++q) {
            const float4 t = pr[5 + q];
            x1[4 * q + 0] = t.x; x1[4 * q + 1] = t.y;
            x1[4 * q + 2] = t.z; x1[4 * q + 3] = t.w;
        }

        unsigned long long a0[10], a1[10];
        #pragma unroll
        for (int q = 0; q < 10; ++q) { a0[q] = sC2[q]; a1[q] = sC2[q]; }

        #pragma unroll
        for (int k = 0; k < D; ++k) {
            const unsigned long long xk0 = pack2(x0[k], x0[k]);
            const unsigned long long xk1 = pack2(x1[k], x1[k]);
            // 5 LDS.128 per k, each feeding 4 FFMA2 (2 m-pairs x 2 rows)
            #pragma unroll
            for (int h = 0; h < 5; ++h) {
                const ulonglong2 mv = ((const ulonglong2*)&sM2[k][0])[h];
                a0[2 * h + 0] = fma2(xk0, mv.x, a0[2 * h + 0]);
                a0[2 * h + 1] = fma2(xk0, mv.y, a0[2 * h + 1]);
                a1[2 * h + 0] = fma2(xk1, mv.x, a1[2 * h + 0]);
                a1[2 * h + 1] = fma2(xk1, mv.y, a1[2 * h + 1]);
            }
        }

        float rs = 0.f;
        #pragma unroll
        for (int q = 0; q < 10; ++q) {
            float l0, h0, l1, h1;
            unpack2(a0[q], l0, h0);
            unpack2(a1[q], l1, h1);
            rs += fmaxf(l0, 0.f) + fmaxf(h0, 0.f)
                + fmaxf(l1, 0.f) + fmaxf(h1, 0.f);
        }
        dacc += (double)rs;
    }

    // odd-row tail
    if ((nrows & 1) && blockIdx.x == 0 && tid == 0) {
        const float* xr = X + (nrows - 1) * D;
        float rs = 0.f;
        for (int m = 0; m < D; ++m) {
            float acc = gC[m];
            for (int k = 0; k < D; ++k) acc += xr[k] * gM[k * D + m];
            rs += fmaxf(acc, 0.f);
        }
        dacc += (double)rs;
    }

    sred[tid] = dacc;
    __syncthreads();
    #pragma unroll
    for (int s = NT / 2; s > 0; s >>= 1) {
        if (tid < s) sred[tid] += sred[tid + s];
        __syncthreads();
    }
    if (tid == 0) g_part[blockIdx.x] = sred[0];
}

// --- kernel 3: final reduce + halving loop --------------------------------
__global__ void __launch_bounds__(256)
finalize_kernel(float* __restrict__ out)
{
    __shared__ double sred[256];
    const int tid = threadIdx.x;

    double acc = 0.0;
    for (int i = tid; i < NB; i += 256) acc += g_part[i];
    sred[tid] = acc;
    __syncthreads();
    #pragma unroll
    for (int s = 128; s > 0; s >>= 1) {
        if (tid < s) sred[tid] += sred[tid + s];
        __syncthreads();
    }
    if (tid == 0) {
        float v = (float)sred[0];
        int n = 0;
        while (v > 1.0f && n < 4096) { v *= 0.5f; ++n; }  // exact /2 halvings
        out[0] = v;
    }
}

// --- kernel 4: padding launch (aligns ncu's 6th-launch capture onto main) --
__global__ void pad_kernel() { g_dummy = (float)g_part[0]; }

extern "C" void kernel_launch(void* const* d_in, const int* in_sizes, int n_in,
                              void* d_out, int out_size)
{
    const float* X = (const float*)d_in[0];
    const float* W = (const float*)d_in[1];
    const float* b = (const float*)d_in[2];
    const float* R = (const float*)d_in[3];
    float* out = (float*)d_out;

    const long long nrows = (long long)in_sizes[0] / D;

    fold_kernel<<<1, 256>>>(W, b, R);            // launch idx 4k+0
    mlp_sum_kernel<<<NB, NT>>>(X, nrows);        // launch idx 4k+1  (idx 5 = this)
    finalize_kernel<<<1, 256>>>(out);            // launch idx 4k+2
    pad_kernel<<<1, 1>>>();                      // launch idx 4k+3
}

// round 5
// speedup vs baseline: 12.1870x; 2.8915x over previous
#include <cuda_runtime.h>
#include <cuda_bf16.h>

// ---------------------------------------------------------------------------
// FixedHiddenMLP -> scalar: scale_to_le1( sum relu( X@M + c ) )
//   M[k][m] = sum_j W[j,k]*R[j,m],  c[m] = sum_j b[j]*R[j,m] + 1
//
// Round 5 (single fused kernel):
//  - coalesced LDG.128 staging of X tiles through smem (kills the nL=32
//    strided-LDG L1tex wavefront storm diagnosed in round 4)
//  - per-block fold of the tiny matmuls (8K FLOP, amortized)
//  - f32x2 FFMA inner loop as round 4 (2 rows/thread, m-pair packing)
//  - last-block reduction with self-resetting atomic counter (graph-safe)
// ---------------------------------------------------------------------------

#define D    20
#define NT   128                 // threads per block
#define NB   1184                // 148 SMs * 8
#define TP   128                 // row-pairs per tile (== NT)
#define PADF 44                  // floats per pair slot in smem (16B-aligned,
                                 // 11 granules -> uniform bank-slot mapping)

__device__ double       g_part[NB];
__device__ unsigned int g_count;   // zero-init; last block resets -> replay-safe

// --- f32x2 helpers ---------------------------------------------------------
__device__ __forceinline__ unsigned long long pack2(float lo, float hi) {
    unsigned long long r;
    asm("mov.b64 %0, {%1, %2};" : "=l"(r) : "f"(lo), "f"(hi));
    return r;
}
__device__ __forceinline__ void unpack2(unsigned long long v, float& lo, float& hi) {
    asm("mov.b64 {%0, %1}, %2;" : "=f"(lo), "=f"(hi) : "l"(v));
}
__device__ __forceinline__ unsigned long long fma2(unsigned long long a,
                                                   unsigned long long b,
                                                   unsigned long long c) {
    unsigned long long d;
    asm("fma.rn.f32x2 %0, %1, %2, %3;" : "=l"(d) : "l"(a), "l"(b), "l"(c));
    return d;
}

__global__ void __launch_bounds__(NT)
fused_mlp_kernel(const float* __restrict__ X,
                 const float* __restrict__ W,
                 const float* __restrict__ bias,
                 const float* __restrict__ R,
                 float* __restrict__ out,
                 long long nrows)
{
    __shared__ unsigned long long sM2[D][10];   // (M[k][2q], M[k][2q+1])
    __shared__ unsigned long long sC2[10];      // (c[2q], c[2q+1])
    __shared__ float  xs[TP * PADF];            // staged X tile, padded pairs
    __shared__ double sred[NT];

    const int tid = threadIdx.x;

    // --- per-block fold of the two tiny matmuls (float view of packed smem) -
    float* sMf = (float*)sM2;   // sMf[k*20 + m] == M[k][m]
    float* sCf = (float*)sC2;   // sCf[m]        == c[m]
    for (int idx = tid; idx < D * D; idx += NT) {
        const int k = idx / D, m = idx % D;
        float acc = 0.f;
        #pragma unroll
        for (int j = 0; j < D; ++j)
            acc += W[j * D + k] * R[j * D + m];
        sMf[k * D + m] = acc;
    }
    if (tid < D) {
        float acc = 1.f;
        #pragma unroll
        for (int j = 0; j < D; ++j)
            acc += bias[j] * R[j * D + tid];
        sCf[tid] = acc;
    }
    // (sync happens inside the tile loop before first use)

    const long long npairs = nrows >> 1;
    const long long ntiles = (npairs + TP - 1) / TP;
    double dacc = 0.0;

    for (long long t = blockIdx.x; t < ntiles; t += gridDim.x) {
        const long long pbase = t * TP;
        const int ptile = (int)((npairs - pbase) < TP ? (npairs - pbase) : TP);
        const int gran  = ptile * 10;    // float4 granules in this tile

        __syncthreads();   // xs reuse guard (also covers fold on first iter)

        // coalesced copy: consecutive threads -> consecutive float4 (4 wf/LDG)
        const float4* __restrict__ src = (const float4*)(X + pbase * (2 * D));
        for (int g = tid; g < gran; g += NT) {
            const int pr = g / 10;          // pair index within tile
            const int pc = g - pr * 10;     // float4 piece within pair
            *(float4*)&xs[pr * PADF + pc * 4] = src[g];
        }
        __syncthreads();

        if (tid < ptile) {
            // load this thread's pair (40 floats) from smem
            float4 xa[10];
            #pragma unroll
            for (int h = 0; h < 10; ++h)
                xa[h] = *(const float4*)&xs[tid * PADF + h * 4];
            float x0[D], x1[D];
            #pragma unroll
            for (int h = 0; h < 5; ++h) {
                x0[4*h+0] = xa[h].x;   x0[4*h+1] = xa[h].y;
                x0[4*h+2] = xa[h].z;   x0[4*h+3] = xa[h].w;
                x1[4*h+0] = xa[5+h].x; x1[4*h+1] = xa[5+h].y;
                x1[4*h+2] = xa[5+h].z; x1[4*h+3] = xa[5+h].w;
            }

            unsigned long long a0[10], a1[10];
            #pragma unroll
            for (int q = 0; q < 10; ++q) { a0[q] = sC2[q]; a1[q] = sC2[q]; }

            #pragma unroll
            for (int k = 0; k < D; ++k) {
                const unsigned long long xk0 = pack2(x0[k], x0[k]);
                const unsigned long long xk1 = pack2(x1[k], x1[k]);
                #pragma unroll
                for (int h = 0; h < 5; ++h) {
                    const ulonglong2 mv = ((const ulonglong2*)&sM2[k][0])[h];
                    a0[2*h+0] = fma2(xk0, mv.x, a0[2*h+0]);
                    a0[2*h+1] = fma2(xk0, mv.y, a0[2*h+1]);
                    a1[2*h+0] = fma2(xk1, mv.x, a1[2*h+0]);
                    a1[2*h+1] = fma2(xk1, mv.y, a1[2*h+1]);
                }
            }

            float rs = 0.f;
            #pragma unroll
            for (int q = 0; q < 10; ++q) {
                float l0, h0, l1, h1;
                unpack2(a0[q], l0, h0);
                unpack2(a1[q], l1, h1);
                rs += fmaxf(l0, 0.f) + fmaxf(h0, 0.f)
                    + fmaxf(l1, 0.f) + fmaxf(h1, 0.f);
            }
            dacc += (double)rs;
        }
    }

    // odd-row tail (nrows is even for this dataset; kept generic)
    if ((nrows & 1) && blockIdx.x == 0 && tid == 0) {
        const float* xr = X + (nrows - 1) * D;
        float rs = 0.f;
        for (int m = 0; m < D; ++m) {
            float acc = sCf[m];
            for (int k = 0; k < D; ++k) acc += xr[k] * sMf[k * D + m];
            rs += fmaxf(acc, 0.f);
        }
        dacc += (double)rs;
    }

    // --- block reduce -------------------------------------------------------
    __syncthreads();           // xs/sred aliasing guard
    sred[tid] = dacc;
    __syncthreads();
    #pragma unroll
    for (int s = NT / 2; s > 0; s >>= 1) {
        if (tid < s) sred[tid] += sred[tid + s];
        __syncthreads();
    }
    if (tid == 0) g_part[blockIdx.x] = sred[0];

    // --- last-block global reduce + halving loop ---------------------------
    __shared__ bool is_last;
    if (tid == 0) {
        __threadfence();
        is_last = (atomicAdd(&g_count, 1u) == (unsigned)(gridDim.x - 1));
    }
    __syncthreads();
    if (is_last) {
        double acc = 0.0;
        for (int i = tid; i < NB; i += NT) acc += g_part[i];
        sred[tid] = acc;
        __syncthreads();
        #pragma unroll
        for (int s = NT / 2; s > 0; s >>= 1) {
            if (tid < s) sred[tid] += sred[tid + s];
            __syncthreads();
        }
        if (tid == 0) {
            float v = (float)sred[0];
            int n = 0;
            while (v > 1.0f && n < 4096) { v *= 0.5f; ++n; }  // exact /2
            out[0] = v;
            g_count = 0;   // reset for next (graph-replayed) call
        }
    }
}

extern "C" void kernel_launch(void* const* d_in, const int* in_sizes, int n_in,
                              void* d_out, int out_size)
{
    const float* X = (const float*)d_in[0];
    const float* W = (const float*)d_in[1];
    const float* b = (const float*)d_in[2];
    const float* R = (const float*)d_in[3];
    float* out = (float*)d_out;

    const long long nrows = (long long)in_sizes[0] / D;

    fused_mlp_kernel<<<NB, NT>>>(X, W, b, R, out, nrows);
}

// round 6
// speedup vs baseline: 13.3869x; 1.0985x over previous
#include <cuda_runtime.h>
#include <cuda_bf16.h>
#include <cstdint>

// ---------------------------------------------------------------------------
// FixedHiddenMLP -> scalar: scale_to_le1( sum relu( X@M + c ) )
//   M[k][m] = sum_j W[j,k]*R[j,m],  c[m] = sum_j b[j]*R[j,m] + 1
//
// Round 6: attack the M-broadcast LDS crossbar (60% L1 in round-5 ncu).
//  - 4 rows/thread: each M LDS.128 now feeds 8 FFMA2 (was 4) -> M crossbar
//    and LSU issue per row halved.
//  - m-chunk-outer / k-inner keeps accumulators at 8 u64 (reg budget ~116).
//  - cp.async staging (global->smem direct, no register round trip).
//  - single fused kernel (clean ncu attribution), last-block finalize.
// ---------------------------------------------------------------------------

#define D   20
#define NT  128                  // threads per block
#define NB  1184                 // 148 SMs * 8
#define TP  512                  // rows per tile (= NT * 4)
#define GSTRIDE 336              // bytes per 4-row group in smem (21*16, pad)

__device__ double       g_part[NB];
__device__ unsigned int g_count;     // zero-init; last block resets

// --- f32x2 helpers ---------------------------------------------------------
__device__ __forceinline__ unsigned long long pack2(float lo, float hi) {
    unsigned long long r;
    asm("mov.b64 %0, {%1, %2};" : "=l"(r) : "f"(lo), "f"(hi));
    return r;
}
__device__ __forceinline__ void unpack2(unsigned long long v, float& lo, float& hi) {
    asm("mov.b64 {%0, %1}, %2;" : "=f"(lo), "=f"(hi) : "l"(v));
}
__device__ __forceinline__ unsigned long long fma2(unsigned long long a,
                                                   unsigned long long b,
                                                   unsigned long long c) {
    unsigned long long d;
    asm("fma.rn.f32x2 %0, %1, %2, %3;" : "=l"(d) : "l"(a), "l"(b), "l"(c));
    return d;
}
__device__ __forceinline__ unsigned long long add2(unsigned long long a,
                                                   unsigned long long b) {
    unsigned long long d;
    asm("add.rn.f32x2 %0, %1, %2;" : "=l"(d) : "l"(a), "l"(b));
    return d;
}

// --- cp.async helpers ------------------------------------------------------
__device__ __forceinline__ uint32_t smem_u32(const void* p) {
    uint32_t a;
    asm("{ .reg .u64 t; cvta.to.shared.u64 t, %1; cvt.u32.u64 %0, t; }"
        : "=r"(a) : "l"(p));
    return a;
}
__device__ __forceinline__ void cpa16(uint32_t dst, const void* src) {
    asm volatile("cp.async.ca.shared.global [%0], [%1], 16;" :: "r"(dst), "l"(src));
}
__device__ __forceinline__ void cpa_commit_wait() {
    asm volatile("cp.async.commit_group;");
    asm volatile("cp.async.wait_group 0;" ::: "memory");
}

__global__ void __launch_bounds__(NT)
fused_mlp_kernel(const float* __restrict__ X,
                 const float* __restrict__ W,
                 const float* __restrict__ bias,
                 const float* __restrict__ R,
                 float* __restrict__ out,
                 long long nrows)
{
    // M as float[k][m] row-major: a u64 at [k][2p] is the natural f32x2
    // m-pair (M[k][2p], M[k][2p+1]).
    __shared__ __align__(16) float sMf[D * D];
    __shared__ __align__(16) float sCf[24];       // c[0..19], padded
    __shared__ __align__(16) unsigned char xs[(TP / 4) * GSTRIDE];  // 43008 B
    __shared__ double sred[NT];

    const int tid = threadIdx.x;

    // --- fold the two tiny matmuls -----------------------------------------
    for (int idx = tid; idx < D * D; idx += NT) {
        const int k = idx / D, m = idx % D;
        float acc = 0.f;
        #pragma unroll
        for (int j = 0; j < D; ++j)
            acc += W[j * D + k] * R[j * D + m];
        sMf[idx] = acc;
    }
    if (tid < D) {
        float acc = 1.f;
        #pragma unroll
        for (int j = 0; j < D; ++j)
            acc += bias[j] * R[j * D + tid];
        sCf[tid] = acc;
    }
    if (tid >= D && tid < 24) sCf[tid] = 0.f;
    __syncthreads();

    const uint32_t xs_base = smem_u32(xs);
    const long long nrows_main = nrows & ~3LL;           // multiple of 4
    const long long ntiles = (nrows_main + TP - 1) / TP;

    double dacc = 0.0;

    for (long long t = blockIdx.x; t < ntiles; t += gridDim.x) {
        const long long row0 = t * TP;
        const int nr = (int)((nrows_main - row0) < TP ? (nrows_main - row0) : TP);
        const int nf4 = nr * 5;                          // float4 granules

        __syncthreads();     // previous compute done before overwriting xs

        // ---- stage via cp.async: coalesced 16B, padded group layout -------
        const char* src = (const char*)(X + row0 * D);
        for (int g = tid; g < nf4; g += NT) {
            const int row = g / 5;
            const int pc  = g - row * 5;
            const uint32_t dst = xs_base + (row >> 2) * GSTRIDE
                                         + (row & 3) * 80 + pc * 16;
            cpa16(dst, src + (size_t)g * 16);
        }
        cpa_commit_wait();
        __syncthreads();

        // ---- compute: this thread owns 4 consecutive rows -----------------
        const long long rbase = row0 + (long long)tid * 4;
        if (rbase < row0 + nr) {
            // load 4 rows (320B) and dup-pack x -> xd[r][k] = (x, x)
            const unsigned char* gp = xs + tid * GSTRIDE;
            unsigned long long xd[4][D];
            #pragma unroll
            for (int r = 0; r < 4; ++r) {
                #pragma unroll
                for (int q = 0; q < 5; ++q) {
                    const float4 v = *(const float4*)(gp + r * 80 + q * 16);
                    xd[r][4 * q + 0] = pack2(v.x, v.x);
                    xd[r][4 * q + 1] = pack2(v.y, v.y);
                    xd[r][4 * q + 2] = pack2(v.z, v.z);
                    xd[r][4 * q + 3] = pack2(v.w, v.w);
                }
            }

            float rs = 0.f;
            #pragma unroll
            for (int h = 0; h < 5; ++h) {       // 4-column chunk (2 m-pairs)
                unsigned long long a0[4], a1[4];
                #pragma unroll
                for (int r = 0; r < 4; ++r) { a0[r] = 0ULL; a1[r] = 0ULL; }

                #pragma unroll
                for (int k = 0; k < D; ++k) {
                    // one broadcast LDS.128 of M feeds 8 FFMA2 (4 rows x 2)
                    const ulonglong2 mv =
                        *(const ulonglong2*)&sMf[k * D + 4 * h];
                    #pragma unroll
                    for (int r = 0; r < 4; ++r) {
                        a0[r] = fma2(xd[r][k], mv.x, a0[r]);
                        a1[r] = fma2(xd[r][k], mv.y, a1[r]);
                    }
                }

                const ulonglong2 cc = *(const ulonglong2*)&sCf[4 * h];
                #pragma unroll
                for (int r = 0; r < 4; ++r) {
                    const unsigned long long s0 = add2(a0[r], cc.x);
                    const unsigned long long s1 = add2(a1[r], cc.y);
                    float l0, h0, l1, h1;
                    unpack2(s0, l0, h0);
                    unpack2(s1, l1, h1);
                    rs += fmaxf(l0, 0.f) + fmaxf(h0, 0.f)
                        + fmaxf(l1, 0.f) + fmaxf(h1, 0.f);
                }
            }
            dacc += (double)rs;     // one DADD per 4 rows: negligible
        }
    }

    // --- generic tail rows (nrows % 4) -------------------------------------
    if (blockIdx.x == 0 && tid == 0) {
        for (long long r = nrows_main; r < nrows; ++r) {
            const float* xr = X + r * D;
            float rs = 0.f;
            for (int m = 0; m < D; ++m) {
                float acc = sCf[m];
                for (int k = 0; k < D; ++k) acc += xr[k] * sMf[k * D + m];
                rs += fmaxf(acc, 0.f);
            }
            dacc += (double)rs;
        }
    }

    // --- block reduce -------------------------------------------------------
    __syncthreads();
    sred[tid] = dacc;
    __syncthreads();
    #pragma unroll
    for (int s = NT / 2; s > 0; s >>= 1) {
        if (tid < s) sred[tid] += sred[tid + s];
        __syncthreads();
    }
    if (tid == 0) g_part[blockIdx.x] = sred[0];

    // --- last-block global reduce + halving loop ---------------------------
    __shared__ bool is_last;
    if (tid == 0) {
        __threadfence();
        is_last = (atomicAdd(&g_count, 1u) == (unsigned)(gridDim.x - 1));
    }
    __syncthreads();
    if (is_last) {
        double acc = 0.0;
        for (int i = tid; i < NB; i += NT) acc += g_part[i];
        sred[tid] = acc;
        __syncthreads();
        #pragma unroll
        for (int s = NT / 2; s > 0; s >>= 1) {
            if (tid < s) sred[tid] += sred[tid + s];
            __syncthreads();
        }
        if (tid == 0) {
            float v = (float)sred[0];
            int n = 0;
            while (v > 1.0f && n < 4096) { v *= 0.5f; ++n; }  // exact /2
            out[0] = v;
            g_count = 0;    // reset for next graph replay
        }
    }
}

extern "C" void kernel_launch(void* const* d_in, const int* in_sizes, int n_in,
                              void* d_out, int out_size)
{
    const float* X = (const float*)d_in[0];
    const float* W = (const float*)d_in[1];
    const float* b = (const float*)d_in[2];
    const float* R = (const float*)d_in[3];
    float* out = (float*)d_out;

    const long long nrows = (long long)in_sizes[0] / D;

    fused_mlp_kernel<<<NB, NT>>>(X, W, b, R, out, nrows);
}